// round 1
// baseline (speedup 1.0000x reference)
#include <cuda_runtime.h>
#include <math.h>
#include <stdint.h>

#define BB 4
#define SS 2048
#define DD 512
#define NH 8
#define DK 64
#define HBC (NH*BB)            // 32 head-batch pairs

// ---------------- scratch (static device globals; no allocation) -------------
__device__ float g_qh[(size_t)HBC*SS*DK];   // [h*B+b][s][dk]
__device__ float g_kh[(size_t)HBC*SS*DK];
__device__ float g_vh[(size_t)HBC*SS*DK];
__device__ float g_ctx[(size_t)BB*SS*DD];   // [b][s][h*dv+d]
__device__ float g_x[(size_t)BB*SS*DD];     // pre-LN (fc + residual)

// ---------------- kernel 1: fused QKV projection -----------------------------
// C = X @ W^T + bias, X in {q,k,v}: [8192,512], W: [512,512] row-major (f,d).
// grid: (128 row-tiles, 24 col-tiles) where col-tile = (mat 0..2, head 0..7).
__global__ __launch_bounds__(256) void qkv_proj_kernel(
    const float* __restrict__ q, const float* __restrict__ k, const float* __restrict__ v,
    const float* __restrict__ wq, const float* __restrict__ bq,
    const float* __restrict__ wk, const float* __restrict__ bk,
    const float* __restrict__ wv, const float* __restrict__ bv)
{
    __shared__ float As[32*68];   // A^T: [c][row]
    __shared__ float Bs[32*68];   // W^T tile: [c][f_local]
    const int t   = threadIdx.x;
    const int mat = blockIdx.y >> 3;
    const int h   = blockIdx.y & 7;
    const int row0 = blockIdx.x * 64;
    const int f0   = h * 64;

    const float* X    = (mat == 0) ? q  : (mat == 1) ? k  : v;
    const float* W    = (mat == 0) ? wq : (mat == 1) ? wk : wv;
    const float* Bias = (mat == 0) ? bq : (mat == 1) ? bk : bv;
    float*       O    = (mat == 0) ? g_qh : (mat == 1) ? g_kh : g_vh;

    const int tx = t & 15, ty = t >> 4;
    float acc[4][4] = {};

    for (int kk = 0; kk < DD; kk += 32) {
#pragma unroll
        for (int i = 0; i < 2; ++i) {
            int fid = t + 256 * i;            // 0..511 float4 slots per tile
            int ar  = fid >> 3;               // 0..63 (row / feature)
            int ac  = (fid & 7) * 4;          // 0..28 (k within tile)
            float4 xa = *(const float4*)&X[(size_t)(row0 + ar) * DD + kk + ac];
            As[(ac+0)*68 + ar] = xa.x;
            As[(ac+1)*68 + ar] = xa.y;
            As[(ac+2)*68 + ar] = xa.z;
            As[(ac+3)*68 + ar] = xa.w;
            float4 wb = *(const float4*)&W[(size_t)(f0 + ar) * DD + kk + ac];
            Bs[(ac+0)*68 + ar] = wb.x;
            Bs[(ac+1)*68 + ar] = wb.y;
            Bs[(ac+2)*68 + ar] = wb.z;
            Bs[(ac+3)*68 + ar] = wb.w;
        }
        __syncthreads();
#pragma unroll
        for (int c = 0; c < 32; ++c) {
            float4 a4 = *(float4*)&As[c*68 + ty*4];
            float4 b4 = *(float4*)&Bs[c*68 + tx*4];
            float av[4] = {a4.x, a4.y, a4.z, a4.w};
            float bv4[4] = {b4.x, b4.y, b4.z, b4.w};
#pragma unroll
            for (int i = 0; i < 4; ++i)
#pragma unroll
                for (int jj = 0; jj < 4; ++jj)
                    acc[i][jj] += av[i] * bv4[jj];
        }
        __syncthreads();
    }

    float4 bias4 = *(const float4*)&Bias[f0 + tx*4];
#pragma unroll
    for (int i = 0; i < 4; ++i) {
        int rg = row0 + ty*4 + i;
        int bb = rg >> 11, ss2 = rg & 2047;
        float4 o;
        o.x = acc[i][0] + bias4.x;
        o.y = acc[i][1] + bias4.y;
        o.z = acc[i][2] + bias4.z;
        o.w = acc[i][3] + bias4.w;
        *(float4*)&O[(((size_t)h*BB + bb)*SS + ss2)*DK + tx*4] = o;
    }
}

// ---------------- kernel 2: attention (scores + softmax + attn-write + PV) ---
// block = (hb, 16 q-rows), 256 threads. Full 16x2048 score strip in smem.
#define SROW 2064                         // padded stride (16*r bank shift)
#define ATTN_SMEM ((16*SROW + 1024 + 64*68) * 4)

__global__ __launch_bounds__(256) void attn_kernel(float* __restrict__ attn_out)
{
    extern __shared__ float sm[];
    float* Ssc = sm;                      // 16 * SROW
    float* Qs  = sm + 16*SROW;            // 16*64 (later reused: Qs[r] = 1/l_r)
    float* KVt = Qs + 1024;               // 64 * 68 (K^T, then V)

    const int hb = blockIdx.y;
    const int q0 = blockIdx.x * 16;
    const int t  = threadIdx.x;
    const int r  = t >> 4, j = t & 15;
    const size_t base = (size_t)hb * SS;

    // load Q tile, fold in 1/temperature = 0.125
    {
        float4 qv = *(const float4*)&g_qh[(base + q0 + r)*DK + j*4];
        qv.x *= 0.125f; qv.y *= 0.125f; qv.z *= 0.125f; qv.w *= 0.125f;
        *(float4*)&Qs[r*DK + j*4] = qv;
    }
    __syncthreads();

    // -------- scores: S[r][k] = Qs[r] . K[k] --------
    for (int k0 = 0; k0 < SS; k0 += 64) {
        const int kk = t >> 2, qd = t & 3;
#pragma unroll
        for (int i = 0; i < 4; ++i) {
            int d0 = (qd*4 + i)*4;
            float4 kv = *(const float4*)&g_kh[(base + k0 + kk)*DK + d0];
            KVt[(d0+0)*68 + kk] = kv.x;
            KVt[(d0+1)*68 + kk] = kv.y;
            KVt[(d0+2)*68 + kk] = kv.z;
            KVt[(d0+3)*68 + kk] = kv.w;
        }
        __syncthreads();
        float a0=0.f, a1=0.f, a2=0.f, a3=0.f;
        const int kb = j*4;
#pragma unroll
        for (int d = 0; d < 64; ++d) {
            float qv = Qs[r*DK + d];
            float4 kv = *(float4*)&KVt[d*68 + kb];
            a0 += qv*kv.x; a1 += qv*kv.y; a2 += qv*kv.z; a3 += qv*kv.w;
        }
        float4 s4 = {a0, a1, a2, a3};
        *(float4*)&Ssc[r*SROW + k0 + kb] = s4;
        __syncthreads();
    }

    // -------- softmax (store unnormalized exp; Qs[r] = 1/sum) --------
    {
        float* row = &Ssc[r*SROW];
        float m = -1e30f;
        for (int kx = j; kx < SS; kx += 16) m = fmaxf(m, row[kx]);
#pragma unroll
        for (int o = 8; o; o >>= 1) m = fmaxf(m, __shfl_xor_sync(0xffffffffu, m, o, 16));
        float l = 0.f;
        for (int kx = j; kx < SS; kx += 16) {
            float e = __expf(row[kx] - m);
            row[kx] = e;
            l += e;
        }
#pragma unroll
        for (int o = 8; o; o >>= 1) l += __shfl_xor_sync(0xffffffffu, l, o, 16);
        if (j == 0) Qs[r] = 1.0f / l;
    }
    __syncthreads();

    // -------- write normalized attention rows (coalesced float4) --------
    for (int rr = 0; rr < 16; ++rr) {
        const float inv = Qs[rr];
        const float* srow = &Ssc[rr*SROW];
        float* arow = &attn_out[(base + q0 + rr) * (size_t)SS];
#pragma unroll
        for (int i = 0; i < 2; ++i) {
            int k4 = (t + 256*i) * 4;
            float4 p = *(const float4*)&srow[k4];
            p.x *= inv; p.y *= inv; p.z *= inv; p.w *= inv;
            *(float4*)&arow[k4] = p;
        }
    }

    // -------- O = P @ V (unnormalized; scale by 1/l at the end) --------
    float o0=0.f, o1=0.f, o2=0.f, o3=0.f;
    const int d4 = j*4;
    for (int k0 = 0; k0 < SS; k0 += 64) {
        __syncthreads();
        const int kk = t >> 2, qd = t & 3;
#pragma unroll
        for (int i = 0; i < 4; ++i) {
            int d0 = (qd*4 + i)*4;
            float4 vv = *(const float4*)&g_vh[(base + k0 + kk)*DK + d0];
            *(float4*)&KVt[kk*68 + d0] = vv;
        }
        __syncthreads();
#pragma unroll
        for (int kk2 = 0; kk2 < 64; ++kk2) {
            float p = Ssc[r*SROW + k0 + kk2];
            float4 vv = *(float4*)&KVt[kk2*68 + d4];
            o0 += p*vv.x; o1 += p*vv.y; o2 += p*vv.z; o3 += p*vv.w;
        }
    }
    const float inv = Qs[r];
    const int h = hb >> 2, b = hb & 3;
    float4 o4 = {o0*inv, o1*inv, o2*inv, o3*inv};
    *(float4*)&g_ctx[(((size_t)b*SS) + q0 + r)*DD + h*DK + d4] = o4;
}

// ---------------- kernel 3: FC + bias + residual -----------------------------
// g_x = g_ctx @ w_fc^T + b_fc + residual(q). grid (128 row-tiles, 8 col-tiles)
__global__ __launch_bounds__(256) void fc_kernel(
    const float* __restrict__ wfc, const float* __restrict__ bfc,
    const float* __restrict__ resid)
{
    __shared__ float As[32*68];
    __shared__ float Bs[32*68];
    const int t = threadIdx.x;
    const int row0 = blockIdx.x * 64;
    const int col0 = blockIdx.y * 64;
    const int tx = t & 15, ty = t >> 4;
    float acc[4][4] = {};

    for (int kk = 0; kk < DD; kk += 32) {
#pragma unroll
        for (int i = 0; i < 2; ++i) {
            int fid = t + 256 * i;
            int ar  = fid >> 3;
            int ac  = (fid & 7) * 4;
            float4 xa = *(const float4*)&g_ctx[(size_t)(row0 + ar) * DD + kk + ac];
            As[(ac+0)*68 + ar] = xa.x;
            As[(ac+1)*68 + ar] = xa.y;
            As[(ac+2)*68 + ar] = xa.z;
            As[(ac+3)*68 + ar] = xa.w;
            float4 wb = *(const float4*)&wfc[(size_t)(col0 + ar) * DD + kk + ac];
            Bs[(ac+0)*68 + ar] = wb.x;
            Bs[(ac+1)*68 + ar] = wb.y;
            Bs[(ac+2)*68 + ar] = wb.z;
            Bs[(ac+3)*68 + ar] = wb.w;
        }
        __syncthreads();
#pragma unroll
        for (int c = 0; c < 32; ++c) {
            float4 a4 = *(float4*)&As[c*68 + ty*4];
            float4 b4 = *(float4*)&Bs[c*68 + tx*4];
            float av[4] = {a4.x, a4.y, a4.z, a4.w};
            float bv4[4] = {b4.x, b4.y, b4.z, b4.w};
#pragma unroll
            for (int i = 0; i < 4; ++i)
#pragma unroll
                for (int jj = 0; jj < 4; ++jj)
                    acc[i][jj] += av[i] * bv4[jj];
        }
        __syncthreads();
    }

    float4 bias4 = *(const float4*)&bfc[col0 + tx*4];
#pragma unroll
    for (int i = 0; i < 4; ++i) {
        int rg = row0 + ty*4 + i;
        float4 r4 = *(const float4*)&resid[(size_t)rg*DD + col0 + tx*4];
        float4 o;
        o.x = acc[i][0] + bias4.x + r4.x;
        o.y = acc[i][1] + bias4.y + r4.y;
        o.z = acc[i][2] + bias4.z + r4.z;
        o.w = acc[i][3] + bias4.w + r4.w;
        *(float4*)&g_x[(size_t)rg*DD + col0 + tx*4] = o;
    }
}

// ---------------- kernel 4: LayerNorm ----------------------------------------
__global__ __launch_bounds__(256) void ln_kernel(
    const float* __restrict__ g, const float* __restrict__ bshift,
    float* __restrict__ out)
{
    const int row = blockIdx.x, t = threadIdx.x;
    const float* xr = &g_x[(size_t)row * DD];
    float x1 = xr[t], x2 = xr[t + 256];
    float s  = x1 + x2;
    float sq = x1*x1 + x2*x2;
#pragma unroll
    for (int o = 16; o; o >>= 1) {
        s  += __shfl_xor_sync(0xffffffffu, s,  o);
        sq += __shfl_xor_sync(0xffffffffu, sq, o);
    }
    __shared__ float ws[8], wq[8];
    if ((t & 31) == 0) { ws[t >> 5] = s; wq[t >> 5] = sq; }
    __syncthreads();
    float S1 = 0.f, S2 = 0.f;
#pragma unroll
    for (int i = 0; i < 8; ++i) { S1 += ws[i]; S2 += wq[i]; }
    const float mu  = S1 * (1.0f / 512.0f);
    const float var = S2 * (1.0f / 512.0f) - mu * mu;
    const float rs  = rsqrtf(var + 1e-5f);
    out[(size_t)row*DD + t]       = (x1 - mu) * rs * g[t]       + bshift[t];
    out[(size_t)row*DD + t + 256] = (x2 - mu) * rs * g[t + 256] + bshift[t + 256];
}

// ---------------- launch ------------------------------------------------------
extern "C" void kernel_launch(void* const* d_in, const int* in_sizes, int n_in,
                              void* d_out, int out_size) {
    const float* q   = (const float*)d_in[0];
    const float* k   = (const float*)d_in[1];
    const float* v   = (const float*)d_in[2];
    const float* wqs = (const float*)d_in[3];
    const float* bqs = (const float*)d_in[4];
    const float* wks = (const float*)d_in[5];
    const float* bks = (const float*)d_in[6];
    const float* wvs = (const float*)d_in[7];
    const float* bvs = (const float*)d_in[8];
    const float* wfc = (const float*)d_in[9];
    const float* bfc = (const float*)d_in[10];
    const float* lng = (const float*)d_in[11];
    const float* lnb = (const float*)d_in[12];

    float* out      = (float*)d_out;
    float* out_attn = out + (size_t)BB * SS * DD;   // x first, then attn

    cudaFuncSetAttribute(attn_kernel,
                         cudaFuncAttributeMaxDynamicSharedMemorySize, ATTN_SMEM);

    qkv_proj_kernel<<<dim3(128, 24), 256>>>(q, k, v, wqs, bqs, wks, bks, wvs, bvs);
    attn_kernel<<<dim3(128, HBC), 256, ATTN_SMEM>>>(out_attn);
    fc_kernel<<<dim3(128, 8), 256>>>(wfc, bfc, q);
    ln_kernel<<<BB * SS, 256>>>(lng, lnb, out);
}

// round 3
// speedup vs baseline: 3.8389x; 3.8389x over previous
#include <cuda_runtime.h>
#include <cuda_bf16.h>
#include <math.h>
#include <stdint.h>

using bf16  = __nv_bfloat16;
using bf162 = __nv_bfloat162;

#define BBATCH 4
#define SSEQ   2048
#define DMOD   512
#define NHEAD  8
#define DKH    64
#define HBC    (NHEAD*BBATCH)          // 32
#define NX     (8192*512)              // tokens x d_model
#define NA     ((size_t)HBC*SSEQ*DKH)  // per-head tensors
#define PAD    40                      // bf16 smem row stride (80B, 16B-aligned)

// ------------------------------ scratch -------------------------------------
__device__ bf16  g_qxh[NX], g_qxl[NX], g_kxh[NX], g_kxl[NX], g_vxh[NX], g_vxl[NX];
__device__ bf16  g_wh[4][512*512], g_wl[4][512*512];   // wq,wk,wv,wfc
__device__ bf16  g_Qh[NA], g_Ql[NA], g_Kh[NA], g_Kl[NA];
__device__ float g_vf[NA];
__device__ bf16  g_Vth[NA], g_Vtl[NA];                  // V transposed [hb][dv][s]
__device__ float g_l[HBC*SSEQ];                          // softmax row sums
__device__ bf16  g_ch[NX], g_cl[NX];                     // ctx splits
__device__ float g_x[NX];                                // pre-LN

// ------------------------------ mma helpers ---------------------------------
__device__ __forceinline__ uint32_t smem_u32(const void* p) {
    return (uint32_t)__cvta_generic_to_shared(p);
}
__device__ __forceinline__ void ldm4(uint32_t a, uint32_t r[4]) {
    asm volatile("ldmatrix.sync.aligned.m8n8.x4.shared.b16 {%0,%1,%2,%3},[%4];"
                 : "=r"(r[0]), "=r"(r[1]), "=r"(r[2]), "=r"(r[3]) : "r"(a));
}
__device__ __forceinline__ void mma_bf16(float c[4], const uint32_t a[4],
                                         uint32_t b0, uint32_t b1) {
    asm volatile(
        "mma.sync.aligned.m16n8k16.row.col.f32.bf16.bf16.f32 "
        "{%0,%1,%2,%3},{%4,%5,%6,%7},{%8,%9},{%0,%1,%2,%3};"
        : "+f"(c[0]), "+f"(c[1]), "+f"(c[2]), "+f"(c[3])
        : "r"(a[0]), "r"(a[1]), "r"(a[2]), "r"(a[3]), "r"(b0), "r"(b1));
}

// 3-term split-bf16 GEMM step over one 128x32 A-chunk and BNx32 B-chunk.
// A row-major [m][k], B row-major [n][k]. Warp tile = 64 x (NT*8).
template<int NT>
__device__ __forceinline__ void mma_3pass(
    const bf16* sAh, const bf16* sAl, const bf16* sBh, const bf16* sBl,
    int lane, int wm, int wn, float (*c)[4])
{
    const int lr = lane & 15;
    const int lc = (lane >> 4) * 8;
#pragma unroll
    for (int ks = 0; ks < 2; ++ks) {
        uint32_t ah[4][4], bh[NT/2][4];
#pragma unroll
        for (int mt = 0; mt < 4; ++mt)
            ldm4(smem_u32(sAh + (wm + mt*16 + lr)*PAD + ks*16 + lc), ah[mt]);
#pragma unroll
        for (int n2 = 0; n2 < NT/2; ++n2)
            ldm4(smem_u32(sBh + (wn + n2*16 + lr)*PAD + ks*16 + lc), bh[n2]);
#pragma unroll
        for (int mt = 0; mt < 4; ++mt)
#pragma unroll
            for (int nt = 0; nt < NT; ++nt)
                mma_bf16(c[mt*NT+nt], ah[mt], bh[nt>>1][nt&1], bh[nt>>1][2+(nt&1)]);
        // pass 2: Al x Bh
        uint32_t al[4][4];
#pragma unroll
        for (int mt = 0; mt < 4; ++mt)
            ldm4(smem_u32(sAl + (wm + mt*16 + lr)*PAD + ks*16 + lc), al[mt]);
#pragma unroll
        for (int mt = 0; mt < 4; ++mt)
#pragma unroll
            for (int nt = 0; nt < NT; ++nt)
                mma_bf16(c[mt*NT+nt], al[mt], bh[nt>>1][nt&1], bh[nt>>1][2+(nt&1)]);
        // pass 3: Ah x Bl
        uint32_t bl[NT/2][4];
#pragma unroll
        for (int n2 = 0; n2 < NT/2; ++n2)
            ldm4(smem_u32(sBl + (wn + n2*16 + lr)*PAD + ks*16 + lc), bl[n2]);
#pragma unroll
        for (int mt = 0; mt < 4; ++mt)
#pragma unroll
            for (int nt = 0; nt < NT; ++nt)
                mma_bf16(c[mt*NT+nt], ah[mt], bl[nt>>1][nt&1], bl[nt>>1][2+(nt&1)]);
    }
}

__device__ __forceinline__ void store_split2(bf16* dh, bf16* dl, float a, float b) {
    bf16 h0 = __float2bfloat16(a), h1 = __float2bfloat16(b);
    bf162 hp; hp.x = h0; hp.y = h1; *(bf162*)dh = hp;
    bf16 l0 = __float2bfloat16(a - __bfloat162float(h0));
    bf16 l1 = __float2bfloat16(b - __bfloat162float(h1));
    bf162 lp; lp.x = l0; lp.y = l1; *(bf162*)dl = lp;
}

// ------------------------- kernel 1: splits + zero ---------------------------
__device__ __forceinline__ void split4(const float* s, bf16* dh, bf16* dl, int j) {
    float4 v = ((const float4*)s)[j];
    bf16 h0 = __float2bfloat16(v.x), h1 = __float2bfloat16(v.y);
    bf16 h2 = __float2bfloat16(v.z), h3 = __float2bfloat16(v.w);
    bf162 p;
    p.x = h0; p.y = h1; ((bf162*)dh)[j*2]   = p;
    p.x = h2; p.y = h3; ((bf162*)dh)[j*2+1] = p;
    bf16 l0 = __float2bfloat16(v.x - __bfloat162float(h0));
    bf16 l1 = __float2bfloat16(v.y - __bfloat162float(h1));
    bf16 l2 = __float2bfloat16(v.z - __bfloat162float(h2));
    bf16 l3 = __float2bfloat16(v.w - __bfloat162float(h3));
    p.x = l0; p.y = l1; ((bf162*)dl)[j*2]   = p;
    p.x = l2; p.y = l3; ((bf162*)dl)[j*2+1] = p;
}

__global__ __launch_bounds__(256) void split_all(
    const float* __restrict__ q, const float* __restrict__ k, const float* __restrict__ v,
    const float* __restrict__ wq, const float* __restrict__ wk, const float* __restrict__ wv,
    const float* __restrict__ wfc)
{
    const int NX4 = NX/4, NW4 = 512*512/4;
    int i = blockIdx.x*256 + threadIdx.x;
    if (i < 3*NX4) {
        int seg = i / NX4, j = i - seg*NX4;
        const float* s = (seg==0) ? q : (seg==1) ? k : v;
        bf16* dh = (seg==0) ? g_qxh : (seg==1) ? g_kxh : g_vxh;
        bf16* dl = (seg==0) ? g_qxl : (seg==1) ? g_kxl : g_vxl;
        split4(s, dh, dl, j);
    } else {
        int j = i - 3*NX4;
        if (j < 4*NW4) {
            int seg = j / NW4, jj = j - seg*NW4;
            const float* s = (seg==0) ? wq : (seg==1) ? wk : (seg==2) ? wv : wfc;
            split4(s, g_wh[seg], g_wl[seg], jj);
        } else {
            int j2 = j - 4*NW4;
            if (j2 < (HBC*SSEQ)/4) ((float4*)g_l)[j2] = make_float4(0.f,0.f,0.f,0.f);
        }
    }
}

// ------------------------- kernel 2: QKV projection --------------------------
__global__ __launch_bounds__(256) void proj_kernel(
    const float* __restrict__ bq, const float* __restrict__ bk, const float* __restrict__ bv)
{
    __shared__ __align__(16) bf16 sAh[128*PAD], sAl[128*PAD], sBh[128*PAD], sBl[128*PAD];
    const int t = threadIdx.x, lane = t & 31, wid = t >> 5;
    const int mat = blockIdx.y >> 2;
    const int n0  = (blockIdx.y & 3) * 128;
    const int m0  = blockIdx.x * 128;
    const bf16* Ah = (mat==0) ? g_qxh : (mat==1) ? g_kxh : g_vxh;
    const bf16* Al = (mat==0) ? g_qxl : (mat==1) ? g_kxl : g_vxl;
    const bf16* Bh = g_wh[mat];
    const bf16* Bl = g_wl[mat];
    const float* Bias = (mat==0) ? bq : (mat==1) ? bk : bv;

    float c[16][4] = {};
    const int wm = (wid >> 2) * 64, wn = (wid & 3) * 32;

    for (int k0 = 0; k0 < 512; k0 += 32) {
#pragma unroll
        for (int i = 0; i < 2; ++i) {
            int id = t + 256*i, r = id >> 2, cc = (id & 3) * 8;
            *(uint4*)&sAh[r*PAD+cc] = *(const uint4*)&Ah[(size_t)(m0+r)*512 + k0+cc];
            *(uint4*)&sAl[r*PAD+cc] = *(const uint4*)&Al[(size_t)(m0+r)*512 + k0+cc];
            *(uint4*)&sBh[r*PAD+cc] = *(const uint4*)&Bh[(size_t)(n0+r)*512 + k0+cc];
            *(uint4*)&sBl[r*PAD+cc] = *(const uint4*)&Bl[(size_t)(n0+r)*512 + k0+cc];
        }
        __syncthreads();
        mma_3pass<4>(sAh, sAl, sBh, sBl, lane, wm, wn, c);
        __syncthreads();
    }

    const int g = lane >> 2, tg = lane & 3;
#pragma unroll
    for (int mt = 0; mt < 4; ++mt) {
        int r1 = m0 + wm + mt*16 + g;
        int r2 = r1 + 8;
#pragma unroll
        for (int nt = 0; nt < 4; ++nt) {
            float* cc = c[mt*4+nt];
            int f = n0 + wn + nt*8 + tg*2;
            float b0 = Bias[f], b1 = Bias[f+1];
            float v0 = cc[0]+b0, v1 = cc[1]+b1, v2 = cc[2]+b0, v3 = cc[3]+b1;
            if (mat == 0) { v0 *= 0.125f; v1 *= 0.125f; v2 *= 0.125f; v3 *= 0.125f; }
            int h = f >> 6, dk = f & 63;
            int bb1 = r1 >> 11, s1 = r1 & 2047;
            int bb2 = r2 >> 11, s2 = r2 & 2047;
            size_t o1 = (((size_t)(h*BBATCH+bb1))*SSEQ + s1)*DKH + dk;
            size_t o2 = (((size_t)(h*BBATCH+bb2))*SSEQ + s2)*DKH + dk;
            if (mat == 2) {
                *(float2*)&g_vf[o1] = make_float2(v0, v1);
                *(float2*)&g_vf[o2] = make_float2(v2, v3);
            } else if (mat == 0) {
                store_split2(g_Qh+o1, g_Ql+o1, v0, v1);
                store_split2(g_Qh+o2, g_Ql+o2, v2, v3);
            } else {
                store_split2(g_Kh+o1, g_Kl+o1, v0, v1);
                store_split2(g_Kh+o2, g_Kl+o2, v2, v3);
            }
        }
    }
}

// ------------------------- kernel 3: V transpose + split ---------------------
__global__ void vtrans_kernel() {
    __shared__ float tile[32][33];
    const int hb = blockIdx.z, s0 = blockIdx.x*32, d0 = blockIdx.y*32;
    const int x = threadIdx.x, y0 = threadIdx.y;
    for (int y = y0; y < 32; y += 8)
        tile[y][x] = g_vf[((size_t)hb*SSEQ + s0 + y)*DKH + d0 + x];
    __syncthreads();
    for (int y = y0; y < 32; y += 8) {
        float val = tile[x][y];
        bf16 h = __float2bfloat16(val);
        bf16 l = __float2bfloat16(val - __bfloat162float(h));
        size_t o = ((size_t)hb*DKH + d0 + y)*SSEQ + s0 + x;
        g_Vth[o] = h; g_Vtl[o] = l;
    }
}

// ------------------------- kernel 4: E = exp(QK^T/8) + row sums --------------
__global__ __launch_bounds__(256) void e_kernel(float* __restrict__ attn) {
    __shared__ __align__(16) bf16 sAh[128*PAD], sAl[128*PAD], sBh[128*PAD], sBl[128*PAD];
    const int t = threadIdx.x, lane = t & 31, wid = t >> 5;
    const int hb = blockIdx.z;
    const int m0 = blockIdx.x * 128, n0 = blockIdx.y * 128;
    float c[16][4] = {};
    const int wm = (wid >> 2) * 64, wn = (wid & 3) * 32;

    for (int k0 = 0; k0 < DKH; k0 += 32) {
#pragma unroll
        for (int i = 0; i < 2; ++i) {
            int id = t + 256*i, r = id >> 2, cc = (id & 3) * 8;
            *(uint4*)&sAh[r*PAD+cc] = *(const uint4*)&g_Qh[((size_t)hb*SSEQ + m0+r)*DKH + k0+cc];
            *(uint4*)&sAl[r*PAD+cc] = *(const uint4*)&g_Ql[((size_t)hb*SSEQ + m0+r)*DKH + k0+cc];
            *(uint4*)&sBh[r*PAD+cc] = *(const uint4*)&g_Kh[((size_t)hb*SSEQ + n0+r)*DKH + k0+cc];
            *(uint4*)&sBl[r*PAD+cc] = *(const uint4*)&g_Kl[((size_t)hb*SSEQ + n0+r)*DKH + k0+cc];
        }
        __syncthreads();
        mma_3pass<4>(sAh, sAl, sBh, sBl, lane, wm, wn, c);
        __syncthreads();
    }

    const int g = lane >> 2, tg = lane & 3;
#pragma unroll
    for (int mt = 0; mt < 4; ++mt) {
        int r1 = m0 + wm + mt*16 + g;
        int r2 = r1 + 8;
        float s1 = 0.f, s2 = 0.f;
#pragma unroll
        for (int nt = 0; nt < 4; ++nt) {
            float* cc = c[mt*4+nt];
            int col = n0 + wn + nt*8 + tg*2;
            float e0 = __expf(cc[0]), e1 = __expf(cc[1]);
            float e2 = __expf(cc[2]), e3 = __expf(cc[3]);
            *(float2*)&attn[((size_t)hb*SSEQ + r1)*SSEQ + col] = make_float2(e0, e1);
            *(float2*)&attn[((size_t)hb*SSEQ + r2)*SSEQ + col] = make_float2(e2, e3);
            s1 += e0 + e1; s2 += e2 + e3;
        }
        s1 += __shfl_xor_sync(0xffffffffu, s1, 1);
        s1 += __shfl_xor_sync(0xffffffffu, s1, 2);
        s2 += __shfl_xor_sync(0xffffffffu, s2, 1);
        s2 += __shfl_xor_sync(0xffffffffu, s2, 2);
        if (tg == 0) {
            atomicAdd(&g_l[hb*SSEQ + r1], s1);
            atomicAdd(&g_l[hb*SSEQ + r2], s2);
        }
    }
}

// ------------------------- kernel 5: normalize + O = P V ---------------------
__global__ __launch_bounds__(256) void pv_kernel(float* __restrict__ attn) {
    __shared__ __align__(16) bf16 sPh[128*PAD], sPl[128*PAD];
    __shared__ __align__(16) bf16 sVh[64*PAD],  sVl[64*PAD];
    __shared__ float sInv[128];
    const int t = threadIdx.x, lane = t & 31, wid = t >> 5;
    const int hb = blockIdx.y;
    const int m0 = blockIdx.x * 128;
    if (t < 128) sInv[t] = 1.0f / g_l[hb*SSEQ + m0 + t];
    __syncthreads();

    float c[8][4] = {};
    const int wm = (wid >> 2) * 64, wn = (wid & 3) * 16;

    for (int k0 = 0; k0 < SSEQ; k0 += 32) {
#pragma unroll
        for (int i = 0; i < 4; ++i) {
            int id = t + 256*i, r = id >> 3, cc = (id & 7) * 4;
            size_t gi = ((size_t)hb*SSEQ + m0 + r)*SSEQ + k0 + cc;
            float4 e4 = *(const float4*)&attn[gi];
            float inv = sInv[r];
            e4.x *= inv; e4.y *= inv; e4.z *= inv; e4.w *= inv;
            *(float4*)&attn[gi] = e4;                 // normalized attn output
            bf16 h0 = __float2bfloat16(e4.x), h1 = __float2bfloat16(e4.y);
            bf16 h2 = __float2bfloat16(e4.z), h3 = __float2bfloat16(e4.w);
            bf162 p;
            p.x = h0; p.y = h1; ((bf162*)&sPh[r*PAD+cc])[0] = p;
            p.x = h2; p.y = h3; ((bf162*)&sPh[r*PAD+cc])[1] = p;
            bf16 l0 = __float2bfloat16(e4.x - __bfloat162float(h0));
            bf16 l1 = __float2bfloat16(e4.y - __bfloat162float(h1));
            bf16 l2 = __float2bfloat16(e4.z - __bfloat162float(h2));
            bf16 l3 = __float2bfloat16(e4.w - __bfloat162float(h3));
            p.x = l0; p.y = l1; ((bf162*)&sPl[r*PAD+cc])[0] = p;
            p.x = l2; p.y = l3; ((bf162*)&sPl[r*PAD+cc])[1] = p;
        }
        {
            int r = t >> 2, cc = (t & 3) * 8;
            *(uint4*)&sVh[r*PAD+cc] = *(const uint4*)&g_Vth[((size_t)hb*DKH + r)*SSEQ + k0+cc];
            *(uint4*)&sVl[r*PAD+cc] = *(const uint4*)&g_Vtl[((size_t)hb*DKH + r)*SSEQ + k0+cc];
        }
        __syncthreads();
        mma_3pass<2>(sPh, sPl, sVh, sVl, lane, wm, wn, c);
        __syncthreads();
    }

    const int g = lane >> 2, tg = lane & 3;
    const int b = hb & 3, h = hb >> 2;
#pragma unroll
    for (int mt = 0; mt < 4; ++mt) {
        int r1 = m0 + wm + mt*16 + g;
        int r2 = r1 + 8;
#pragma unroll
        for (int nt = 0; nt < 2; ++nt) {
            float* cc = c[mt*2+nt];
            int col = wn + nt*8 + tg*2;
            size_t o1 = ((size_t)(b*SSEQ + r1))*DMOD + h*DKH + col;
            size_t o2 = ((size_t)(b*SSEQ + r2))*DMOD + h*DKH + col;
            store_split2(g_ch+o1, g_cl+o1, cc[0], cc[1]);
            store_split2(g_ch+o2, g_cl+o2, cc[2], cc[3]);
        }
    }
}

// ------------------------- kernel 6: FC + bias + residual --------------------
__global__ __launch_bounds__(256) void fc_kernel(
    const float* __restrict__ bfc, const float* __restrict__ resid)
{
    __shared__ __align__(16) bf16 sAh[128*PAD], sAl[128*PAD], sBh[128*PAD], sBl[128*PAD];
    const int t = threadIdx.x, lane = t & 31, wid = t >> 5;
    const int n0 = blockIdx.y * 128;
    const int m0 = blockIdx.x * 128;
    float c[16][4] = {};
    const int wm = (wid >> 2) * 64, wn = (wid & 3) * 32;

    for (int k0 = 0; k0 < 512; k0 += 32) {
#pragma unroll
        for (int i = 0; i < 2; ++i) {
            int id = t + 256*i, r = id >> 2, cc = (id & 3) * 8;
            *(uint4*)&sAh[r*PAD+cc] = *(const uint4*)&g_ch[(size_t)(m0+r)*512 + k0+cc];
            *(uint4*)&sAl[r*PAD+cc] = *(const uint4*)&g_cl[(size_t)(m0+r)*512 + k0+cc];
            *(uint4*)&sBh[r*PAD+cc] = *(const uint4*)&g_wh[3][(size_t)(n0+r)*512 + k0+cc];
            *(uint4*)&sBl[r*PAD+cc] = *(const uint4*)&g_wl[3][(size_t)(n0+r)*512 + k0+cc];
        }
        __syncthreads();
        mma_3pass<4>(sAh, sAl, sBh, sBl, lane, wm, wn, c);
        __syncthreads();
    }

    const int g = lane >> 2, tg = lane & 3;
#pragma unroll
    for (int mt = 0; mt < 4; ++mt) {
        int r1 = m0 + wm + mt*16 + g;
        int r2 = r1 + 8;
#pragma unroll
        for (int nt = 0; nt < 4; ++nt) {
            float* cc = c[mt*4+nt];
            int d = n0 + wn + nt*8 + tg*2;
            float b0 = bfc[d], b1 = bfc[d+1];
            float v0 = cc[0] + b0 + resid[(size_t)r1*512 + d];
            float v1 = cc[1] + b1 + resid[(size_t)r1*512 + d + 1];
            float v2 = cc[2] + b0 + resid[(size_t)r2*512 + d];
            float v3 = cc[3] + b1 + resid[(size_t)r2*512 + d + 1];
            *(float2*)&g_x[(size_t)r1*512 + d] = make_float2(v0, v1);
            *(float2*)&g_x[(size_t)r2*512 + d] = make_float2(v2, v3);
        }
    }
}

// ------------------------- kernel 7: LayerNorm -------------------------------
__global__ __launch_bounds__(256) void ln_kernel(
    const float* __restrict__ gam, const float* __restrict__ bet,
    float* __restrict__ out)
{
    const int row = blockIdx.x, t = threadIdx.x;
    const float* xr = &g_x[(size_t)row * DMOD];
    float x1 = xr[t], x2 = xr[t + 256];
    float s  = x1 + x2;
    float sq = x1*x1 + x2*x2;
#pragma unroll
    for (int o = 16; o; o >>= 1) {
        s  += __shfl_xor_sync(0xffffffffu, s,  o);
        sq += __shfl_xor_sync(0xffffffffu, sq, o);
    }
    __shared__ float ws[8], wq[8];
    if ((t & 31) == 0) { ws[t >> 5] = s; wq[t >> 5] = sq; }
    __syncthreads();
    float S1 = 0.f, S2 = 0.f;
#pragma unroll
    for (int i = 0; i < 8; ++i) { S1 += ws[i]; S2 += wq[i]; }
    const float mu  = S1 * (1.0f / 512.0f);
    const float var = S2 * (1.0f / 512.0f) - mu * mu;
    const float rs  = rsqrtf(var + 1e-5f);
    out[(size_t)row*DMOD + t]       = (x1 - mu) * rs * gam[t]       + bet[t];
    out[(size_t)row*DMOD + t + 256] = (x2 - mu) * rs * gam[t + 256] + bet[t + 256];
}

// ------------------------- launch --------------------------------------------
extern "C" void kernel_launch(void* const* d_in, const int* in_sizes, int n_in,
                              void* d_out, int out_size) {
    const float* q   = (const float*)d_in[0];
    const float* k   = (const float*)d_in[1];
    const float* v   = (const float*)d_in[2];
    const float* wqs = (const float*)d_in[3];
    const float* bqs = (const float*)d_in[4];
    const float* wks = (const float*)d_in[5];
    const float* bks = (const float*)d_in[6];
    const float* wvs = (const float*)d_in[7];
    const float* bvs = (const float*)d_in[8];
    const float* wfc = (const float*)d_in[9];
    const float* bfc = (const float*)d_in[10];
    const float* lng = (const float*)d_in[11];
    const float* lnb = (const float*)d_in[12];

    float* out      = (float*)d_out;
    float* out_attn = out + (size_t)BBATCH * SSEQ * DMOD;

    const int nsplit = 3*(NX/4) + 4*(512*512/4) + (HBC*SSEQ)/4;
    split_all<<<(nsplit + 255)/256, 256>>>(q, k, v, wqs, wks, wvs, wfc);
    proj_kernel<<<dim3(64, 12), 256>>>(bqs, bks, bvs);
    vtrans_kernel<<<dim3(64, 2, 32), dim3(32, 8)>>>();
    e_kernel<<<dim3(16, 16, 32), 256>>>(out_attn);
    pv_kernel<<<dim3(16, 32), 256>>>(out_attn);
    fc_kernel<<<dim3(64, 4), 256>>>(bfc, q);
    ln_kernel<<<BBATCH * SSEQ, 256>>>(lng, lnb, out);
}

// round 4
// speedup vs baseline: 5.3195x; 1.3857x over previous
#include <cuda_runtime.h>
#include <cuda_bf16.h>
#include <math.h>
#include <stdint.h>

using bf16  = __nv_bfloat16;
using bf162 = __nv_bfloat162;

#define BBATCH 4
#define SSEQ   2048
#define DMOD   512
#define NHEAD  8
#define DKH    64
#define HBC    (NHEAD*BBATCH)          // 32
#define NX     (8192*512)              // tokens x d_model
#define NA     ((size_t)HBC*SSEQ*DKH)  // per-head tensors
#define PAD    40                      // bf16 smem row stride (80B, 16B-aligned)

// stage sizes (bf16 units)
#define TILE_SZ   (128*PAD)            // 5120
#define STG_GEMM  (4*TILE_SZ)          // Ah,Al,Bh,Bl = 20480
#define SMEM_GEMM (2*STG_GEMM*2)       // bytes = 81920
#define VTILE_SZ  (64*PAD)             // 2560
#define STG_PV    (2*TILE_SZ + 2*VTILE_SZ)  // 15360
#define SMEM_PV   (2*STG_PV*2 + 512)   // bytes = 61952

// ------------------------------ scratch -------------------------------------
__device__ bf16  g_qxh[NX], g_qxl[NX], g_kxh[NX], g_kxl[NX], g_vxh[NX], g_vxl[NX];
__device__ bf16  g_wh[4][512*512], g_wl[4][512*512];   // wq,wk,wv,wfc
__device__ bf16  g_Qh[NA], g_Ql[NA], g_Kh[NA], g_Kl[NA];
__device__ float g_vf[NA];
__device__ bf16  g_Vth[NA], g_Vtl[NA];                  // V transposed [hb][dv][s]
__device__ float g_l[HBC*SSEQ];                          // softmax row sums
__device__ bf16  g_ch[NX], g_cl[NX];                     // ctx splits
__device__ float g_x[NX];                                // pre-LN

// ------------------------------ helpers -------------------------------------
__device__ __forceinline__ uint32_t smem_u32(const void* p) {
    return (uint32_t)__cvta_generic_to_shared(p);
}
__device__ __forceinline__ void cp16(void* s, const void* g) {
    asm volatile("cp.async.ca.shared.global [%0], [%1], 16;"
                 :: "r"(smem_u32(s)), "l"(g));
}
__device__ __forceinline__ void cp_commit() {
    asm volatile("cp.async.commit_group;" ::: "memory");
}
__device__ __forceinline__ void cp_wait0() {
    asm volatile("cp.async.wait_group 0;" ::: "memory");
}
__device__ __forceinline__ void ldm4(uint32_t a, uint32_t r[4]) {
    asm volatile("ldmatrix.sync.aligned.m8n8.x4.shared.b16 {%0,%1,%2,%3},[%4];"
                 : "=r"(r[0]), "=r"(r[1]), "=r"(r[2]), "=r"(r[3]) : "r"(a));
}
__device__ __forceinline__ void mma_bf16(float c[4], const uint32_t a[4],
                                         uint32_t b0, uint32_t b1) {
    asm volatile(
        "mma.sync.aligned.m16n8k16.row.col.f32.bf16.bf16.f32 "
        "{%0,%1,%2,%3},{%4,%5,%6,%7},{%8,%9},{%0,%1,%2,%3};"
        : "+f"(c[0]), "+f"(c[1]), "+f"(c[2]), "+f"(c[3])
        : "r"(a[0]), "r"(a[1]), "r"(a[2]), "r"(a[3]), "r"(b0), "r"(b1));
}

// 3-term split-bf16 step. A row-major [m][k], B row-major [n][k].
template<int NT>
__device__ __forceinline__ void mma_3pass(
    const bf16* sAh, const bf16* sAl, const bf16* sBh, const bf16* sBl,
    int lane, int wm, int wn, float (*c)[4])
{
    const int lr = lane & 15;
    const int lc = (lane >> 4) * 8;
#pragma unroll
    for (int ks = 0; ks < 2; ++ks) {
        uint32_t ah[4][4], bh[NT/2][4];
#pragma unroll
        for (int mt = 0; mt < 4; ++mt)
            ldm4(smem_u32(sAh + (wm + mt*16 + lr)*PAD + ks*16 + lc), ah[mt]);
#pragma unroll
        for (int n2 = 0; n2 < NT/2; ++n2)
            ldm4(smem_u32(sBh + (wn + n2*16 + lr)*PAD + ks*16 + lc), bh[n2]);
#pragma unroll
        for (int mt = 0; mt < 4; ++mt)
#pragma unroll
            for (int nt = 0; nt < NT; ++nt)
                mma_bf16(c[mt*NT+nt], ah[mt], bh[nt>>1][nt&1], bh[nt>>1][2+(nt&1)]);
        uint32_t al[4][4];
#pragma unroll
        for (int mt = 0; mt < 4; ++mt)
            ldm4(smem_u32(sAl + (wm + mt*16 + lr)*PAD + ks*16 + lc), al[mt]);
#pragma unroll
        for (int mt = 0; mt < 4; ++mt)
#pragma unroll
            for (int nt = 0; nt < NT; ++nt)
                mma_bf16(c[mt*NT+nt], al[mt], bh[nt>>1][nt&1], bh[nt>>1][2+(nt&1)]);
        uint32_t bl[NT/2][4];
#pragma unroll
        for (int n2 = 0; n2 < NT/2; ++n2)
            ldm4(smem_u32(sBl + (wn + n2*16 + lr)*PAD + ks*16 + lc), bl[n2]);
#pragma unroll
        for (int mt = 0; mt < 4; ++mt)
#pragma unroll
            for (int nt = 0; nt < NT; ++nt)
                mma_bf16(c[mt*NT+nt], ah[mt], bl[nt>>1][nt&1], bl[nt>>1][2+(nt&1)]);
    }
}

__device__ __forceinline__ void store_split2(bf16* dh, bf16* dl, float a, float b) {
    bf16 h0 = __float2bfloat16(a), h1 = __float2bfloat16(b);
    bf162 hp; hp.x = h0; hp.y = h1; *(bf162*)dh = hp;
    bf16 l0 = __float2bfloat16(a - __bfloat162float(h0));
    bf16 l1 = __float2bfloat16(b - __bfloat162float(h1));
    bf162 lp; lp.x = l0; lp.y = l1; *(bf162*)dl = lp;
}

// ------------------------- kernel 1: splits + zero ---------------------------
__device__ __forceinline__ void split4(const float* s, bf16* dh, bf16* dl, int j) {
    float4 v = ((const float4*)s)[j];
    bf16 h0 = __float2bfloat16(v.x), h1 = __float2bfloat16(v.y);
    bf16 h2 = __float2bfloat16(v.z), h3 = __float2bfloat16(v.w);
    bf162 p;
    p.x = h0; p.y = h1; ((bf162*)dh)[j*2]   = p;
    p.x = h2; p.y = h3; ((bf162*)dh)[j*2+1] = p;
    bf16 l0 = __float2bfloat16(v.x - __bfloat162float(h0));
    bf16 l1 = __float2bfloat16(v.y - __bfloat162float(h1));
    bf16 l2 = __float2bfloat16(v.z - __bfloat162float(h2));
    bf16 l3 = __float2bfloat16(v.w - __bfloat162float(h3));
    p.x = l0; p.y = l1; ((bf162*)dl)[j*2]   = p;
    p.x = l2; p.y = l3; ((bf162*)dl)[j*2+1] = p;
}

__global__ __launch_bounds__(256) void split_all(
    const float* __restrict__ q, const float* __restrict__ k, const float* __restrict__ v,
    const float* __restrict__ wq, const float* __restrict__ wk, const float* __restrict__ wv,
    const float* __restrict__ wfc)
{
    const int NX4 = NX/4, NW4 = 512*512/4;
    int i = blockIdx.x*256 + threadIdx.x;
    if (i < 3*NX4) {
        int seg = i / NX4, j = i - seg*NX4;
        const float* s = (seg==0) ? q : (seg==1) ? k : v;
        bf16* dh = (seg==0) ? g_qxh : (seg==1) ? g_kxh : g_vxh;
        bf16* dl = (seg==0) ? g_qxl : (seg==1) ? g_kxl : g_vxl;
        split4(s, dh, dl, j);
    } else {
        int j = i - 3*NX4;
        if (j < 4*NW4) {
            int seg = j / NW4, jj = j - seg*NW4;
            const float* s = (seg==0) ? wq : (seg==1) ? wk : (seg==2) ? wv : wfc;
            split4(s, g_wh[seg], g_wl[seg], jj);
        } else {
            int j2 = j - 4*NW4;
            if (j2 < (HBC*SSEQ)/4) ((float4*)g_l)[j2] = make_float4(0.f,0.f,0.f,0.f);
        }
    }
}

// ------------------------- kernel 2: QKV projection --------------------------
__global__ __launch_bounds__(256) void proj_kernel(
    const float* __restrict__ bq, const float* __restrict__ bk, const float* __restrict__ bv)
{
    extern __shared__ __align__(16) bf16 smp[];
    const int t = threadIdx.x, lane = t & 31, wid = t >> 5;
    const int mat = blockIdx.y >> 2;
    const int n0  = (blockIdx.y & 3) * 128;
    const int m0  = blockIdx.x * 128;
    const bf16* Ah = (mat==0) ? g_qxh : (mat==1) ? g_kxh : g_vxh;
    const bf16* Al = (mat==0) ? g_qxl : (mat==1) ? g_kxl : g_vxl;
    const bf16* Bh = g_wh[mat];
    const bf16* Bl = g_wl[mat];
    const float* Bias = (mat==0) ? bq : (mat==1) ? bk : bv;

    float c[16][4] = {};
    const int wm = (wid >> 2) * 64, wn = (wid & 3) * 32;

    auto load = [&](int st, int k0) {
        bf16* s = smp + st*STG_GEMM;
#pragma unroll
        for (int i = 0; i < 2; ++i) {
            int id = t + 256*i, r = id >> 2, cc = (id & 3) * 8;
            cp16(&s[r*PAD+cc],            &Ah[(size_t)(m0+r)*512 + k0+cc]);
            cp16(&s[TILE_SZ + r*PAD+cc],  &Al[(size_t)(m0+r)*512 + k0+cc]);
            cp16(&s[2*TILE_SZ + r*PAD+cc],&Bh[(size_t)(n0+r)*512 + k0+cc]);
            cp16(&s[3*TILE_SZ + r*PAD+cc],&Bl[(size_t)(n0+r)*512 + k0+cc]);
        }
    };

    load(0, 0); cp_commit();
    for (int i = 0; i < 16; ++i) {
        cp_wait0();
        __syncthreads();
        if (i + 1 < 16) { load((i+1)&1, (i+1)*32); cp_commit(); }
        bf16* s = smp + (i&1)*STG_GEMM;
        mma_3pass<4>(s, s+TILE_SZ, s+2*TILE_SZ, s+3*TILE_SZ, lane, wm, wn, c);
    }

    const int g = lane >> 2, tg = lane & 3;
#pragma unroll
    for (int mt = 0; mt < 4; ++mt) {
        int r1 = m0 + wm + mt*16 + g;
        int r2 = r1 + 8;
#pragma unroll
        for (int nt = 0; nt < 4; ++nt) {
            float* cc = c[mt*4+nt];
            int f = n0 + wn + nt*8 + tg*2;
            float b0 = Bias[f], b1 = Bias[f+1];
            float v0 = cc[0]+b0, v1 = cc[1]+b1, v2 = cc[2]+b0, v3 = cc[3]+b1;
            if (mat == 0) { v0 *= 0.125f; v1 *= 0.125f; v2 *= 0.125f; v3 *= 0.125f; }
            int h = f >> 6, dk = f & 63;
            int bb1 = r1 >> 11, s1 = r1 & 2047;
            int bb2 = r2 >> 11, s2 = r2 & 2047;
            size_t o1 = (((size_t)(h*BBATCH+bb1))*SSEQ + s1)*DKH + dk;
            size_t o2 = (((size_t)(h*BBATCH+bb2))*SSEQ + s2)*DKH + dk;
            if (mat == 2) {
                *(float2*)&g_vf[o1] = make_float2(v0, v1);
                *(float2*)&g_vf[o2] = make_float2(v2, v3);
            } else if (mat == 0) {
                store_split2(g_Qh+o1, g_Ql+o1, v0, v1);
                store_split2(g_Qh+o2, g_Ql+o2, v2, v3);
            } else {
                store_split2(g_Kh+o1, g_Kl+o1, v0, v1);
                store_split2(g_Kh+o2, g_Kl+o2, v2, v3);
            }
        }
    }
}

// ------------------------- kernel 3: V transpose + split ---------------------
__global__ void vtrans_kernel() {
    __shared__ float tile[32][33];
    const int hb = blockIdx.z, s0 = blockIdx.x*32, d0 = blockIdx.y*32;
    const int x = threadIdx.x, y0 = threadIdx.y;
    for (int y = y0; y < 32; y += 8)
        tile[y][x] = g_vf[((size_t)hb*SSEQ + s0 + y)*DKH + d0 + x];
    __syncthreads();
    for (int y = y0; y < 32; y += 8) {
        float val = tile[x][y];
        bf16 h = __float2bfloat16(val);
        bf16 l = __float2bfloat16(val - __bfloat162float(h));
        size_t o = ((size_t)hb*DKH + d0 + y)*SSEQ + s0 + x;
        g_Vth[o] = h; g_Vtl[o] = l;
    }
}

// ------------------------- kernel 4: E = exp(QK^T/8) + row sums --------------
__global__ __launch_bounds__(256) void e_kernel(float* __restrict__ attn) {
    extern __shared__ __align__(16) bf16 smp[];
    const int t = threadIdx.x, lane = t & 31, wid = t >> 5;
    const int hb = blockIdx.z;
    const int m0 = blockIdx.x * 128, n0 = blockIdx.y * 128;
    float c[16][4] = {};
    const int wm = (wid >> 2) * 64, wn = (wid & 3) * 32;

    auto load = [&](int st, int k0) {
        bf16* s = smp + st*STG_GEMM;
#pragma unroll
        for (int i = 0; i < 2; ++i) {
            int id = t + 256*i, r = id >> 2, cc = (id & 3) * 8;
            cp16(&s[r*PAD+cc],            &g_Qh[((size_t)hb*SSEQ + m0+r)*DKH + k0+cc]);
            cp16(&s[TILE_SZ + r*PAD+cc],  &g_Ql[((size_t)hb*SSEQ + m0+r)*DKH + k0+cc]);
            cp16(&s[2*TILE_SZ + r*PAD+cc],&g_Kh[((size_t)hb*SSEQ + n0+r)*DKH + k0+cc]);
            cp16(&s[3*TILE_SZ + r*PAD+cc],&g_Kl[((size_t)hb*SSEQ + n0+r)*DKH + k0+cc]);
        }
    };

    load(0, 0); cp_commit();
    for (int i = 0; i < 2; ++i) {
        cp_wait0();
        __syncthreads();
        if (i + 1 < 2) { load((i+1)&1, 32); cp_commit(); }
        bf16* s = smp + (i&1)*STG_GEMM;
        mma_3pass<4>(s, s+TILE_SZ, s+2*TILE_SZ, s+3*TILE_SZ, lane, wm, wn, c);
    }

    const int g = lane >> 2, tg = lane & 3;
#pragma unroll
    for (int mt = 0; mt < 4; ++mt) {
        int r1 = m0 + wm + mt*16 + g;
        int r2 = r1 + 8;
        float s1 = 0.f, s2 = 0.f;
#pragma unroll
        for (int nt = 0; nt < 4; ++nt) {
            float* cc = c[mt*4+nt];
            int col = n0 + wn + nt*8 + tg*2;
            float e0 = __expf(cc[0]), e1 = __expf(cc[1]);
            float e2 = __expf(cc[2]), e3 = __expf(cc[3]);
            *(float2*)&attn[((size_t)hb*SSEQ + r1)*SSEQ + col] = make_float2(e0, e1);
            *(float2*)&attn[((size_t)hb*SSEQ + r2)*SSEQ + col] = make_float2(e2, e3);
            s1 += e0 + e1; s2 += e2 + e3;
        }
        s1 += __shfl_xor_sync(0xffffffffu, s1, 1);
        s1 += __shfl_xor_sync(0xffffffffu, s1, 2);
        s2 += __shfl_xor_sync(0xffffffffu, s2, 1);
        s2 += __shfl_xor_sync(0xffffffffu, s2, 2);
        if (tg == 0) {
            atomicAdd(&g_l[hb*SSEQ + r1], s1);
            atomicAdd(&g_l[hb*SSEQ + r2], s2);
        }
    }
}

// ------------------------- kernel 5: normalize + O = P V ---------------------
__global__ __launch_bounds__(256) void pv_kernel(float* __restrict__ attn) {
    extern __shared__ __align__(16) bf16 smp[];
    float* sInv = (float*)(smp + 2*STG_PV);
    const int t = threadIdx.x, lane = t & 31, wid = t >> 5;
    const int hb = blockIdx.y;
    const int m0 = blockIdx.x * 128;
    if (t < 128) sInv[t] = 1.0f / g_l[hb*SSEQ + m0 + t];
    __syncthreads();

    float c[8][4] = {};
    const int wm = (wid >> 2) * 64, wn = (wid & 3) * 16;

    auto ldP = [&](int k0, float4* pe) {
#pragma unroll
        for (int i = 0; i < 4; ++i) {
            int id = t + 256*i, r = id >> 3, cc = (id & 7) * 4;
            pe[i] = *(const float4*)&attn[((size_t)hb*SSEQ + m0 + r)*SSEQ + k0 + cc];
        }
    };
    auto stP = [&](int st, int k0, const float4* pe) {
        bf16* Ph = smp + st*STG_PV;
        bf16* Pl = Ph + TILE_SZ;
#pragma unroll
        for (int i = 0; i < 4; ++i) {
            int id = t + 256*i, r = id >> 3, cc = (id & 7) * 4;
            float inv = sInv[r];
            float4 e4 = pe[i];
            e4.x *= inv; e4.y *= inv; e4.z *= inv; e4.w *= inv;
            *(float4*)&attn[((size_t)hb*SSEQ + m0 + r)*SSEQ + k0 + cc] = e4;
            bf16 h0 = __float2bfloat16(e4.x), h1 = __float2bfloat16(e4.y);
            bf16 h2 = __float2bfloat16(e4.z), h3 = __float2bfloat16(e4.w);
            bf162 p;
            p.x = h0; p.y = h1; ((bf162*)&Ph[r*PAD+cc])[0] = p;
            p.x = h2; p.y = h3; ((bf162*)&Ph[r*PAD+cc])[1] = p;
            bf16 l0 = __float2bfloat16(e4.x - __bfloat162float(h0));
            bf16 l1 = __float2bfloat16(e4.y - __bfloat162float(h1));
            bf16 l2 = __float2bfloat16(e4.z - __bfloat162float(h2));
            bf16 l3 = __float2bfloat16(e4.w - __bfloat162float(h3));
            p.x = l0; p.y = l1; ((bf162*)&Pl[r*PAD+cc])[0] = p;
            p.x = l2; p.y = l3; ((bf162*)&Pl[r*PAD+cc])[1] = p;
        }
    };
    auto ldV = [&](int st, int k0) {
        bf16* Vh = smp + st*STG_PV + 2*TILE_SZ;
        bf16* Vl = Vh + VTILE_SZ;
        int r = t >> 2, cc = (t & 3) * 8;
        cp16(&Vh[r*PAD+cc], &g_Vth[((size_t)hb*DKH + r)*SSEQ + k0+cc]);
        cp16(&Vl[r*PAD+cc], &g_Vtl[((size_t)hb*DKH + r)*SSEQ + k0+cc]);
    };

    float4 pe[4];
    ldP(0, pe);
    ldV(0, 0); cp_commit();
    stP(0, 0, pe);

    for (int i = 0; i < 64; ++i) {
        cp_wait0();
        __syncthreads();
        if (i + 1 < 64) {
            ldP((i+1)*32, pe);                 // LDGs in flight during mma
            ldV((i+1)&1, (i+1)*32); cp_commit();
        }
        bf16* s = smp + (i&1)*STG_PV;
        mma_3pass<2>(s, s+TILE_SZ, s+2*TILE_SZ, s+2*TILE_SZ+VTILE_SZ, lane, wm, wn, c);
        if (i + 1 < 64) stP((i+1)&1, (i+1)*32, pe);
    }

    const int g = lane >> 2, tg = lane & 3;
    const int b = hb & 3, h = hb >> 2;
#pragma unroll
    for (int mt = 0; mt < 4; ++mt) {
        int r1 = m0 + wm + mt*16 + g;
        int r2 = r1 + 8;
#pragma unroll
        for (int nt = 0; nt < 2; ++nt) {
            float* cc = c[mt*2+nt];
            int col = wn + nt*8 + tg*2;
            size_t o1 = ((size_t)(b*SSEQ + r1))*DMOD + h*DKH + col;
            size_t o2 = ((size_t)(b*SSEQ + r2))*DMOD + h*DKH + col;
            store_split2(g_ch+o1, g_cl+o1, cc[0], cc[1]);
            store_split2(g_ch+o2, g_cl+o2, cc[2], cc[3]);
        }
    }
}

// ------------------------- kernel 6: FC + bias + residual --------------------
__global__ __launch_bounds__(256) void fc_kernel(
    const float* __restrict__ bfc, const float* __restrict__ resid)
{
    extern __shared__ __align__(16) bf16 smp[];
    const int t = threadIdx.x, lane = t & 31, wid = t >> 5;
    const int n0 = blockIdx.y * 128;
    const int m0 = blockIdx.x * 128;
    float c[16][4] = {};
    const int wm = (wid >> 2) * 64, wn = (wid & 3) * 32;

    auto load = [&](int st, int k0) {
        bf16* s = smp + st*STG_GEMM;
#pragma unroll
        for (int i = 0; i < 2; ++i) {
            int id = t + 256*i, r = id >> 2, cc = (id & 3) * 8;
            cp16(&s[r*PAD+cc],            &g_ch[(size_t)(m0+r)*512 + k0+cc]);
            cp16(&s[TILE_SZ + r*PAD+cc],  &g_cl[(size_t)(m0+r)*512 + k0+cc]);
            cp16(&s[2*TILE_SZ + r*PAD+cc],&g_wh[3][(size_t)(n0+r)*512 + k0+cc]);
            cp16(&s[3*TILE_SZ + r*PAD+cc],&g_wl[3][(size_t)(n0+r)*512 + k0+cc]);
        }
    };

    load(0, 0); cp_commit();
    for (int i = 0; i < 16; ++i) {
        cp_wait0();
        __syncthreads();
        if (i + 1 < 16) { load((i+1)&1, (i+1)*32); cp_commit(); }
        bf16* s = smp + (i&1)*STG_GEMM;
        mma_3pass<4>(s, s+TILE_SZ, s+2*TILE_SZ, s+3*TILE_SZ, lane, wm, wn, c);
    }

    const int g = lane >> 2, tg = lane & 3;
#pragma unroll
    for (int mt = 0; mt < 4; ++mt) {
        int r1 = m0 + wm + mt*16 + g;
        int r2 = r1 + 8;
#pragma unroll
        for (int nt = 0; nt < 4; ++nt) {
            float* cc = c[mt*4+nt];
            int d = n0 + wn + nt*8 + tg*2;
            float b0 = bfc[d], b1 = bfc[d+1];
            float v0 = cc[0] + b0 + resid[(size_t)r1*512 + d];
            float v1 = cc[1] + b1 + resid[(size_t)r1*512 + d + 1];
            float v2 = cc[2] + b0 + resid[(size_t)r2*512 + d];
            float v3 = cc[3] + b1 + resid[(size_t)r2*512 + d + 1];
            *(float2*)&g_x[(size_t)r1*512 + d] = make_float2(v0, v1);
            *(float2*)&g_x[(size_t)r2*512 + d] = make_float2(v2, v3);
        }
    }
}

// ------------------------- kernel 7: LayerNorm -------------------------------
__global__ __launch_bounds__(256) void ln_kernel(
    const float* __restrict__ gam, const float* __restrict__ bet,
    float* __restrict__ out)
{
    const int row = blockIdx.x, t = threadIdx.x;
    const float* xr = &g_x[(size_t)row * DMOD];
    float x1 = xr[t], x2 = xr[t + 256];
    float s  = x1 + x2;
    float sq = x1*x1 + x2*x2;
#pragma unroll
    for (int o = 16; o; o >>= 1) {
        s  += __shfl_xor_sync(0xffffffffu, s,  o);
        sq += __shfl_xor_sync(0xffffffffu, sq, o);
    }
    __shared__ float ws[8], wq[8];
    if ((t & 31) == 0) { ws[t >> 5] = s; wq[t >> 5] = sq; }
    __syncthreads();
    float S1 = 0.f, S2 = 0.f;
#pragma unroll
    for (int i = 0; i < 8; ++i) { S1 += ws[i]; S2 += wq[i]; }
    const float mu  = S1 * (1.0f / 512.0f);
    const float var = S2 * (1.0f / 512.0f) - mu * mu;
    const float rs  = rsqrtf(var + 1e-5f);
    out[(size_t)row*DMOD + t]       = (x1 - mu) * rs * gam[t]       + bet[t];
    out[(size_t)row*DMOD + t + 256] = (x2 - mu) * rs * gam[t + 256] + bet[t + 256];
}

// ------------------------- launch --------------------------------------------
extern "C" void kernel_launch(void* const* d_in, const int* in_sizes, int n_in,
                              void* d_out, int out_size) {
    const float* q   = (const float*)d_in[0];
    const float* k   = (const float*)d_in[1];
    const float* v   = (const float*)d_in[2];
    const float* wqs = (const float*)d_in[3];
    const float* bqs = (const float*)d_in[4];
    const float* wks = (const float*)d_in[5];
    const float* bks = (const float*)d_in[6];
    const float* wvs = (const float*)d_in[7];
    const float* bvs = (const float*)d_in[8];
    const float* wfc = (const float*)d_in[9];
    const float* bfc = (const float*)d_in[10];
    const float* lng = (const float*)d_in[11];
    const float* lnb = (const float*)d_in[12];

    float* out      = (float*)d_out;
    float* out_attn = out + (size_t)BBATCH * SSEQ * DMOD;

    cudaFuncSetAttribute(proj_kernel, cudaFuncAttributeMaxDynamicSharedMemorySize, SMEM_GEMM);
    cudaFuncSetAttribute(e_kernel,    cudaFuncAttributeMaxDynamicSharedMemorySize, SMEM_GEMM);
    cudaFuncSetAttribute(pv_kernel,   cudaFuncAttributeMaxDynamicSharedMemorySize, SMEM_PV);
    cudaFuncSetAttribute(fc_kernel,   cudaFuncAttributeMaxDynamicSharedMemorySize, SMEM_GEMM);

    const int nsplit = 3*(NX/4) + 4*(512*512/4) + (HBC*SSEQ)/4;
    split_all<<<(nsplit + 255)/256, 256>>>(q, k, v, wqs, wks, wvs, wfc);
    proj_kernel<<<dim3(64, 12), 256, SMEM_GEMM>>>(bqs, bks, bvs);
    vtrans_kernel<<<dim3(64, 2, 32), dim3(32, 8)>>>();
    e_kernel<<<dim3(16, 16, 32), 256, SMEM_GEMM>>>(out_attn);
    pv_kernel<<<dim3(16, 32), 256, SMEM_PV>>>(out_attn);
    fc_kernel<<<dim3(64, 4), 256, SMEM_GEMM>>>(bfc, q);
    ln_kernel<<<BBATCH * SSEQ, 256>>>(lng, lnb, out);
}